// round 2
// baseline (speedup 1.0000x reference)
#include <cuda_runtime.h>
#include <math.h>
#include <stdint.h>

// Problem shape (fixed by the dataset)
#define NB    32
#define CD    256      // d_model
#define HWSZ  4096     // 64*64
#define NTOK  131072   // NB*HWSZ
#define KCODE 1024

static __device__ float g_esq[KCODE];
static __device__ float g_xsq[NTOK];
static __device__ int   g_idx[NTOK];
static __device__ int   g_counts[KCODE];
static __device__ float g_segsum[KCODE * CD];
static __device__ float g_usage[KCODE];

#define DECAYF 0.99f
#define OMD    ((float)(1.0 - 0.99))          // 0.01f, computed as reference does
#define EPSF   1e-7f
#define KEPSF  ((float)(1024 * 1e-7))         // K * EPS

// packed fp32x2 helpers (sm_103a FFMA2 path — ptxas never auto-emits this)
#define FFMA2(d, a, b, c) \
    asm("fma.rn.f32x2 %0, %1, %2, %3;" \
        : "=l"(d) : "l"(a), "l"(b), "l"(c))
#define PACK2(out, x) \
    asm("mov.b64 %0, {%1, %1};" : "=l"(out) : "r"(__float_as_uint(x)))
#define UNPACK2(lo, hi, in) \
    asm("mov.b64 {%0, %1}, %2;" : "=r"(lo), "=r"(hi) : "l"(in))

// ---------------------------------------------------------------------------
// zero scratch (runs every graph replay, before atomics)
__global__ void zero_kernel() {
    int i = blockIdx.x * 256 + threadIdx.x;
    if (i < KCODE * CD) g_segsum[i] = 0.0f;
    if (i < KCODE)      g_counts[i] = 0;
}

// ---------------------------------------------------------------------------
// z [B, C, H, W] -> encoded_flat [N, C]   (also output #0)
__global__ __launch_bounds__(256) void transpose_kernel(
    const float* __restrict__ z, float* __restrict__ enc)
{
    __shared__ float tile[32][33];
    int hw0 = blockIdx.x * 32;
    int c0  = blockIdx.y * 32;
    int b   = blockIdx.z;
    int x = threadIdx.x, y = threadIdx.y;   // block (32, 8)
    const float* zb = z + (size_t)b * CD * HWSZ;
#pragma unroll
    for (int j = 0; j < 32; j += 8)
        tile[y + j][x] = zb[(size_t)(c0 + y + j) * HWSZ + hw0 + x];
    __syncthreads();
    float* eb = enc + ((size_t)b * HWSZ + hw0) * CD + c0;
#pragma unroll
    for (int j = 0; j < 32; j += 8)
        eb[(size_t)(y + j) * CD + x] = tile[x][y + j];
}

// ---------------------------------------------------------------------------
// per-row squared norms (64 threads per row, row = blockIdx.x)
__global__ void esq_kernel(const float* __restrict__ emb) {
    int row = blockIdx.x, tid = threadIdx.x;
    float4 v = ((const float4*)(emb + (size_t)row * CD))[tid];
    float s = v.x * v.x + v.y * v.y + v.z * v.z + v.w * v.w;
#pragma unroll
    for (int o = 16; o > 0; o >>= 1) s += __shfl_down_sync(0xffffffffu, s, o);
    __shared__ float sh[2];
    if ((tid & 31) == 0) sh[tid >> 5] = s;
    __syncthreads();
    if (tid == 0) g_esq[row] = sh[0] + sh[1];
}

__global__ void xsq_kernel(const float* __restrict__ enc) {
    int row = blockIdx.x, tid = threadIdx.x;
    float4 v = ((const float4*)(enc + (size_t)row * CD))[tid];
    float s = v.x * v.x + v.y * v.y + v.z * v.z + v.w * v.w;
#pragma unroll
    for (int o = 16; o > 0; o >>= 1) s += __shfl_down_sync(0xffffffffu, s, o);
    __shared__ float sh[2];
    if ((tid & 31) == 0) sh[tid >> 5] = s;
    __syncthreads();
    if (tid == 0) g_xsq[row] = sh[0] + sh[1];
}

// ---------------------------------------------------------------------------
// Fused distance + argmin. Tile: 64 tokens x 128 codes, 4x8 per thread.
//   As: [64 tok][256 k] row-major (64 KB), resident for the block
//   Bs: DOUBLE-buffered [64 k][128 codes + 4 pad] (2 x 33 KB), streamed
//   Inner product via packed fma.rn.f32x2 (2 codes per instruction).
//   best: 64 packed (dist_bits<<32 | idx) keys, atomicMin == jnp.argmin tiebreak
#define BS_STRIDE 132
#define BS_ELEMS  (64 * BS_STRIDE)
#define ARGMIN_SMEM (64 * 256 * 4 + 2 * BS_ELEMS * 4 + 64 * 8)

__global__ __launch_bounds__(256) void argmin_kernel(
    const float* __restrict__ enc, const float* __restrict__ emb)
{
    extern __shared__ float smem[];
    float* As  = smem;                            // 64*256
    float* Bs0 = smem + 64 * 256;                 // buffer 0
    float* Bs1 = Bs0 + BS_ELEMS;                  // buffer 1
    unsigned long long* best = (unsigned long long*)(Bs1 + BS_ELEMS);

    const int tid = threadIdx.x;
    const int n0  = blockIdx.x * 64;

    // load A tile (row-major, straight float4 copy — conflict-free)
#pragma unroll
    for (int i = 0; i < 16; i++) {
        int t   = tid + i * 256;              // float4 index, 0..4095
        int tok = t >> 6;
        int k4  = (t & 63) << 2;
        float4 v = *(const float4*)(enc + (((size_t)(n0 + tok)) << 8) + k4);
        *(float4*)&As[tok * 256 + k4] = v;
    }
    if (tid < 64) best[tid] = 0x7F800000FFFFFFFFULL;   // (+inf, idx=max)

    const int tx = tid & 15;        // code group: codes tx*8 .. tx*8+7
    const int ty = tid >> 4;        // token group: tokens ty*4 .. ty*4+3

    // per-thread decomposition of the B-chunk copy (8 float4s per thread)
    // chunk m: cc = (m>>2)*128, kk = (m&3)*64; element: code = t>>4, k4 = (t&15)<<2
    float4 breg[8];

    // prologue: fetch chunk 0
#pragma unroll
    for (int i = 0; i < 8; i++) {
        int t = tid + i * 256;
        breg[i] = *(const float4*)(emb + (((size_t)(t >> 4)) << 8) + ((t & 15) << 2));
    }
    {   // store chunk 0 into buffer 0 (transposed [k][code])
#pragma unroll
        for (int i = 0; i < 8; i++) {
            int t = tid + i * 256;
            int code = t >> 4;
            int k4   = (t & 15) << 2;
            Bs0[(k4 + 0) * BS_STRIDE + code] = breg[i].x;
            Bs0[(k4 + 1) * BS_STRIDE + code] = breg[i].y;
            Bs0[(k4 + 2) * BS_STRIDE + code] = breg[i].z;
            Bs0[(k4 + 3) * BS_STRIDE + code] = breg[i].w;
        }
    }
    __syncthreads();

    unsigned long long accp[4][4];   // 4 tokens x 4 code-pairs (8 codes)

    for (int m = 0; m < 32; m++) {
        const int cc = (m >> 2) << 7;        // code-tile base
        const int kk = (m & 3) << 6;         // k-chunk base
        const float* Bb = (m & 1) ? Bs1 : Bs0;
        float* Bn       = (m & 1) ? Bs0 : Bs1;

        // prefetch next chunk from gmem (latency hidden under compute)
        if (m < 31) {
            int cc2 = ((m + 1) >> 2) << 7;
            int kk2 = ((m + 1) & 3) << 6;
#pragma unroll
            for (int i = 0; i < 8; i++) {
                int t = tid + i * 256;
                breg[i] = *(const float4*)(emb +
                    (((size_t)(cc2 + (t >> 4))) << 8) + kk2 + ((t & 15) << 2));
            }
        }

        if ((m & 3) == 0) {
#pragma unroll
            for (int i = 0; i < 4; i++)
#pragma unroll
                for (int j = 0; j < 4; j++) accp[i][j] = 0ULL;
        }

        const float* a0p = As + (ty * 4 + 0) * 256 + kk;
        const float* a1p = As + (ty * 4 + 1) * 256 + kk;
        const float* a2p = As + (ty * 4 + 2) * 256 + kk;
        const float* a3p = As + (ty * 4 + 3) * 256 + kk;
        const float* bp  = Bb + tx * 8;

#pragma unroll 16
        for (int k = 0; k < 64; k++) {
            unsigned long long pa0, pa1, pa2, pa3;
            PACK2(pa0, a0p[k]);
            PACK2(pa1, a1p[k]);
            PACK2(pa2, a2p[k]);
            PACK2(pa3, a3p[k]);
            double2 bA = *(const double2*)(bp + k * BS_STRIDE);
            double2 bB = *(const double2*)(bp + k * BS_STRIDE + 4);
            unsigned long long pb0 = __double_as_longlong(bA.x);
            unsigned long long pb1 = __double_as_longlong(bA.y);
            unsigned long long pb2 = __double_as_longlong(bB.x);
            unsigned long long pb3 = __double_as_longlong(bB.y);
            FFMA2(accp[0][0], pa0, pb0, accp[0][0]);
            FFMA2(accp[0][1], pa0, pb1, accp[0][1]);
            FFMA2(accp[0][2], pa0, pb2, accp[0][2]);
            FFMA2(accp[0][3], pa0, pb3, accp[0][3]);
            FFMA2(accp[1][0], pa1, pb0, accp[1][0]);
            FFMA2(accp[1][1], pa1, pb1, accp[1][1]);
            FFMA2(accp[1][2], pa1, pb2, accp[1][2]);
            FFMA2(accp[1][3], pa1, pb3, accp[1][3]);
            FFMA2(accp[2][0], pa2, pb0, accp[2][0]);
            FFMA2(accp[2][1], pa2, pb1, accp[2][1]);
            FFMA2(accp[2][2], pa2, pb2, accp[2][2]);
            FFMA2(accp[2][3], pa2, pb3, accp[2][3]);
            FFMA2(accp[3][0], pa3, pb0, accp[3][0]);
            FFMA2(accp[3][1], pa3, pb1, accp[3][1]);
            FFMA2(accp[3][2], pa3, pb2, accp[3][2]);
            FFMA2(accp[3][3], pa3, pb3, accp[3][3]);
        }

        // store prefetched chunk into the other buffer
        if (m < 31) {
#pragma unroll
            for (int i = 0; i < 8; i++) {
                int t = tid + i * 256;
                int code = t >> 4;
                int k4   = (t & 15) << 2;
                Bn[(k4 + 0) * BS_STRIDE + code] = breg[i].x;
                Bn[(k4 + 1) * BS_STRIDE + code] = breg[i].y;
                Bn[(k4 + 2) * BS_STRIDE + code] = breg[i].z;
                Bn[(k4 + 3) * BS_STRIDE + code] = breg[i].w;
            }
            __syncthreads();
        }

        // fold this 4x8 tile of distances into per-token best
        if ((m & 3) == 3) {
            float esq[8];
#pragma unroll
            for (int j = 0; j < 8; j++) esq[j] = g_esq[cc + tx * 8 + j];
#pragma unroll
            for (int i = 0; i < 4; i++) {
                float xsq = g_xsq[n0 + ty * 4 + i];
                float dot[8];
#pragma unroll
                for (int j = 0; j < 4; j++) {
                    unsigned lo, hi;
                    UNPACK2(lo, hi, accp[i][j]);
                    dot[2 * j]     = __uint_as_float(lo);
                    dot[2 * j + 1] = __uint_as_float(hi);
                }
                float bd = __int_as_float(0x7f800000);
                int bi = 0;
#pragma unroll
                for (int j = 0; j < 8; j++) {
                    // (x^2 - 2*dot) + e^2, exactly the reference association
                    float d = __fadd_rn(__fadd_rn(xsq, -__fmul_rn(2.0f, dot[j])), esq[j]);
                    if (d < bd) { bd = d; bi = cc + tx * 8 + j; }   // strict < keeps first min
                }
                unsigned long long key =
                    ((unsigned long long)__float_as_uint(bd) << 32) | (unsigned)bi;
                atomicMin(&best[ty * 4 + i], key);
            }
        }
    }
    __syncthreads();
    if (tid < 64)
        g_idx[n0 + tid] = (int)(unsigned)(best[tid] & 0xFFFFFFFFULL);
}

// ---------------------------------------------------------------------------
// Per 32-token tile: write quantized_flat, quantized (transposed), float idx,
// counts, and segment sums of encoded rows.
__global__ __launch_bounds__(256) void scatter_kernel(
    const float* __restrict__ enc, const float* __restrict__ emb,
    float* __restrict__ qf, float* __restrict__ quant, float* __restrict__ idx_out)
{
    __shared__ float rows[32][CD + 1];
    __shared__ int sidx[32];
    int tid = threadIdx.x;
    int n0  = blockIdx.x * 32;

    if (tid < 32) {
        int idx = g_idx[n0 + tid];
        sidx[tid] = idx;
        idx_out[n0 + tid] = (float)idx;
        atomicAdd(&g_counts[idx], 1);
    }
    __syncthreads();

    for (int r = 0; r < 32; r++) {
        int idx = sidx[r];
        float e = emb[(((size_t)idx) << 8) + tid];
        float x = enc[(((size_t)(n0 + r)) << 8) + tid];
        // straight-through: x + (e - x), matching reference rounding
        float qv = __fadd_rn(x, __fadd_rn(e, -x));
        rows[r][tid] = qv;
        qf[(((size_t)(n0 + r)) << 8) + tid] = qv;
        atomicAdd(&g_segsum[(((size_t)idx) << 8) + tid], x);
    }
    __syncthreads();

    int b   = n0 >> 12;
    int hw0 = n0 & 4095;
    int x   = tid & 31;
    for (int c = tid >> 5; c < CD; c += 8)
        quant[(((size_t)b << 8) + c) * HWSZ + hw0 + x] = rows[x][c];
}

// ---------------------------------------------------------------------------
__global__ void usage_kernel(const float* __restrict__ usage_in,
                             float* __restrict__ out_usage)
{
    int k = threadIdx.x;   // 1024 threads
    float u = __fadd_rn(__fmul_rn(usage_in[k], DECAYF),
                        __fmul_rn((float)g_counts[k], OMD));
    __shared__ float red[32];
    __shared__ float n_sh;
    float v = u;
#pragma unroll
    for (int o = 16; o > 0; o >>= 1) v += __shfl_down_sync(0xffffffffu, v, o);
    if ((k & 31) == 0) red[k >> 5] = v;
    __syncthreads();
    if (k < 32) {
        float s = red[k];
#pragma unroll
        for (int o = 16; o > 0; o >>= 1) s += __shfl_down_sync(0xffffffffu, s, o);
        if (k == 0) n_sh = s;
    }
    __syncthreads();
    float n = n_sh;
    float nu = __fmul_rn(__fdiv_rn(__fadd_rn(u, EPSF), __fadd_rn(n, KEPSF)), n);
    out_usage[k] = nu;
    g_usage[k] = nu;
}

__global__ void final_kernel(const float* __restrict__ code_avg,
                             float* __restrict__ new_avg,
                             float* __restrict__ new_emb)
{
    int k = blockIdx.x, c = threadIdx.x;
    size_t i = (((size_t)k) << 8) + c;
    float avg = __fadd_rn(__fmul_rn(code_avg[i], DECAYF),
                          __fmul_rn(OMD, g_segsum[i]));
    new_avg[i] = avg;
    new_emb[i] = __fdiv_rn(avg, g_usage[k]);
}

// ---------------------------------------------------------------------------
extern "C" void kernel_launch(void* const* d_in, const int* in_sizes, int n_in,
                              void* d_out, int out_size)
{
    const float* z        = (const float*)d_in[0];
    const float* emb      = (const float*)d_in[1];
    const float* usage    = (const float*)d_in[2];
    const float* code_avg = (const float*)d_in[3];

    float* out       = (float*)d_out;
    float* enc       = out;                                   // [N, 256]
    float* qf        = enc + (size_t)NTOK * CD;               // [N, 256]
    float* idx_out   = qf + (size_t)NTOK * CD;                // [N]
    float* quant     = idx_out + NTOK;                        // [B, 256, H, W]
    float* new_emb   = quant + (size_t)NTOK * CD;             // [K, 256]
    float* new_usage = new_emb + (size_t)KCODE * CD;          // [K]
    float* new_avg   = new_usage + KCODE;                     // [K, 256]

    cudaFuncSetAttribute(argmin_kernel,
                         cudaFuncAttributeMaxDynamicSharedMemorySize, ARGMIN_SMEM);

    zero_kernel<<<KCODE, 256>>>();
    transpose_kernel<<<dim3(HWSZ / 32, CD / 32, NB), dim3(32, 8)>>>(z, enc);
    esq_kernel<<<KCODE, 64>>>(emb);
    xsq_kernel<<<NTOK, 64>>>(enc);
    argmin_kernel<<<NTOK / 64, 256, ARGMIN_SMEM>>>(enc, emb);
    scatter_kernel<<<NTOK / 32, 256>>>(enc, emb, qf, quant, idx_out);
    usage_kernel<<<1, 1024>>>(usage, new_usage);
    final_kernel<<<KCODE, CD>>>(code_avg, new_avg, new_emb);
}

// round 4
// speedup vs baseline: 1.1218x; 1.1218x over previous
#include <cuda_runtime.h>
#include <math.h>
#include <stdint.h>

// Problem shape (fixed by the dataset)
#define NB    32
#define CD    256      // d_model
#define HWSZ  4096     // 64*64
#define NTOK  131072   // NB*HWSZ
#define KCODE 1024

static __device__ float g_esq[KCODE];
static __device__ int   g_idx[NTOK];
static __device__ int   g_counts[KCODE];
static __device__ float g_segsum[KCODE * CD];
static __device__ float g_usage[KCODE];

#define DECAYF 0.99f
#define OMD    ((float)(1.0 - 0.99))          // 0.01f, computed as reference does
#define EPSF   1e-7f
#define KEPSF  ((float)(1024 * 1e-7))         // K * EPS

// packed fp32x2 helpers (sm_103a FFMA2 path — ptxas never auto-emits this)
#define FFMA2(d, a, b, c) \
    asm("fma.rn.f32x2 %0, %1, %2, %3;" \
        : "=l"(d) : "l"(a), "l"(b), "l"(c))
#define PACK2(out, x) \
    asm("mov.b64 %0, {%1, %1};" : "=l"(out) : "r"(__float_as_uint(x)))
#define UNPACK2(lo, hi, in) \
    asm("mov.b64 {%0, %1}, %2;" : "=r"(lo), "=r"(hi) : "l"(in))

// ---------------------------------------------------------------------------
// zero scratch (runs every graph replay, before atomics)
__global__ void zero_kernel() {
    int i = blockIdx.x * 256 + threadIdx.x;
    if (i < KCODE * CD) g_segsum[i] = 0.0f;
    if (i < KCODE)      g_counts[i] = 0;
}

// ---------------------------------------------------------------------------
// z [B, C, H, W] -> encoded_flat [N, C]   (also output #0)
__global__ __launch_bounds__(256) void transpose_kernel(
    const float* __restrict__ z, float* __restrict__ enc)
{
    __shared__ float tile[32][33];
    int hw0 = blockIdx.x * 32;
    int c0  = blockIdx.y * 32;
    int b   = blockIdx.z;
    int x = threadIdx.x, y = threadIdx.y;   // block (32, 8)
    const float* zb = z + (size_t)b * CD * HWSZ;
#pragma unroll
    for (int j = 0; j < 32; j += 8)
        tile[y + j][x] = zb[(size_t)(c0 + y + j) * HWSZ + hw0 + x];
    __syncthreads();
    float* eb = enc + ((size_t)b * HWSZ + hw0) * CD + c0;
#pragma unroll
    for (int j = 0; j < 32; j += 8)
        eb[(size_t)(y + j) * CD + x] = tile[x][y + j];
}

// ---------------------------------------------------------------------------
// per-row squared norms of the codebook (64 threads per row)
__global__ void esq_kernel(const float* __restrict__ emb) {
    int row = blockIdx.x, tid = threadIdx.x;
    float4 v = ((const float4*)(emb + (size_t)row * CD))[tid];
    float s = v.x * v.x + v.y * v.y + v.z * v.z + v.w * v.w;
#pragma unroll
    for (int o = 16; o > 0; o >>= 1) s += __shfl_down_sync(0xffffffffu, s, o);
    __shared__ float sh[2];
    if ((tid & 31) == 0) sh[tid >> 5] = s;
    __syncthreads();
    if (tid == 0) g_esq[row] = sh[0] + sh[1];
}

// ---------------------------------------------------------------------------
// Fused distance + argmin (+ per-token x^2 computed from the resident A tile).
// Tile: 64 tokens x 128 codes, 4x8 per thread, packed fma.rn.f32x2.
//   As: [64 tok][260 pad] (66.5 KB, stride 260 de-conflicts broadcast a-loads)
//   Bs: single buffer [64 k][128 codes + 4 pad] (33 KB); next chunk prefetched
//       into registers during compute, stored after a sync (2 BAR/chunk)
//   ~101 KB smem/block -> 2 blocks/SM -> 4 warps/SMSP for latency hiding
//   best: 64 packed (dist_bits<<32 | idx) keys, atomicMin == jnp.argmin tiebreak
#define AS_STRIDE 260
#define BS_STRIDE 132
#define BS_ELEMS  (64 * BS_STRIDE)
#define ARGMIN_SMEM (64 * AS_STRIDE * 4 + BS_ELEMS * 4 + 64 * 8 + 64 * 4)

__global__ __launch_bounds__(256) void argmin_kernel(
    const float* __restrict__ enc, const float* __restrict__ emb)
{
    extern __shared__ float smem[];
    float* As = smem;                                   // 64*260
    float* Bs = smem + 64 * AS_STRIDE;                  // 64*132
    unsigned long long* best = (unsigned long long*)(Bs + BS_ELEMS);
    float* sxsq = (float*)(best + 64);                  // 64 per-token x^2

    const int tid = threadIdx.x;
    const int n0  = blockIdx.x * 64;

    // load A tile (row-major float4 copy — conflict-free)
#pragma unroll
    for (int i = 0; i < 16; i++) {
        int t   = tid + i * 256;              // float4 index, 0..4095
        int tok = t >> 6;
        int k4  = (t & 63) << 2;
        float4 v = *(const float4*)(enc + (((size_t)(n0 + tok)) << 8) + k4);
        *(float4*)&As[tok * AS_STRIDE + k4] = v;
    }
    if (tid < 64) best[tid] = 0x7F800000FFFFFFFFULL;   // (+inf, idx=max)
    __syncthreads();

    // per-token x^2 from the smem tile: 4 threads per token, 64 floats each
    {
        int tok  = tid >> 2;
        int part = tid & 3;
        const float* ap = As + tok * AS_STRIDE + part * 64;
        float s = 0.0f;
#pragma unroll
        for (int i = 0; i < 16; i++) {
            float4 v = *(const float4*)(ap + i * 4);
            s += v.x * v.x + v.y * v.y + v.z * v.z + v.w * v.w;
        }
        s += __shfl_xor_sync(0xffffffffu, s, 1);
        s += __shfl_xor_sync(0xffffffffu, s, 2);
        if (part == 0) sxsq[tok] = s;
    }

    const int tx = tid & 15;        // code group: codes tx*8 .. tx*8+7
    const int ty = tid >> 4;        // token group: tokens ty*4 .. ty*4+3

    // per-thread decomposition of the B-chunk copy (8 float4s per thread)
    float4 breg[8];

    // prologue: fetch + store chunk 0 (cc=0, kk=0)
#pragma unroll
    for (int i = 0; i < 8; i++) {
        int t = tid + i * 256;
        breg[i] = *(const float4*)(emb + (((size_t)(t >> 4)) << 8) + ((t & 15) << 2));
    }
#pragma unroll
    for (int i = 0; i < 8; i++) {
        int t = tid + i * 256;
        int code = t >> 4;
        int k4   = (t & 15) << 2;
        Bs[(k4 + 0) * BS_STRIDE + code] = breg[i].x;
        Bs[(k4 + 1) * BS_STRIDE + code] = breg[i].y;
        Bs[(k4 + 2) * BS_STRIDE + code] = breg[i].z;
        Bs[(k4 + 3) * BS_STRIDE + code] = breg[i].w;
    }
    __syncthreads();

    unsigned long long accp[4][4];   // 4 tokens x 4 code-pairs (8 codes)

    for (int m = 0; m < 32; m++) {
        const int cc = (m >> 2) << 7;        // code-tile base
        const int kk = (m & 3) << 6;         // k-chunk base

        // prefetch next chunk from gmem (latency hidden under compute)
        if (m < 31) {
            int cc2 = ((m + 1) >> 2) << 7;
            int kk2 = ((m + 1) & 3) << 6;
#pragma unroll
            for (int i = 0; i < 8; i++) {
                int t = tid + i * 256;
                breg[i] = *(const float4*)(emb +
                    (((size_t)(cc2 + (t >> 4))) << 8) + kk2 + ((t & 15) << 2));
            }
        }

        if ((m & 3) == 0) {
#pragma unroll
            for (int i = 0; i < 4; i++)
#pragma unroll
                for (int j = 0; j < 4; j++) accp[i][j] = 0ULL;
        }

        const float* a0p = As + (ty * 4 + 0) * AS_STRIDE + kk;
        const float* a1p = As + (ty * 4 + 1) * AS_STRIDE + kk;
        const float* a2p = As + (ty * 4 + 2) * AS_STRIDE + kk;
        const float* a3p = As + (ty * 4 + 3) * AS_STRIDE + kk;
        const float* bp  = Bs + tx * 8;

        // unroll 8: body ~26 instr/iter -> ~3.3 KB, stays inside the 6 KB L0 I$
#pragma unroll 8
        for (int k = 0; k < 64; k++) {
            unsigned long long pa0, pa1, pa2, pa3;
            PACK2(pa0, a0p[k]);
            PACK2(pa1, a1p[k]);
            PACK2(pa2, a2p[k]);
            PACK2(pa3, a3p[k]);
            double2 bA = *(const double2*)(bp + k * BS_STRIDE);
            double2 bB = *(const double2*)(bp + k * BS_STRIDE + 4);
            unsigned long long pb0 = __double_as_longlong(bA.x);
            unsigned long long pb1 = __double_as_longlong(bA.y);
            unsigned long long pb2 = __double_as_longlong(bB.x);
            unsigned long long pb3 = __double_as_longlong(bB.y);
            FFMA2(accp[0][0], pa0, pb0, accp[0][0]);
            FFMA2(accp[0][1], pa0, pb1, accp[0][1]);
            FFMA2(accp[0][2], pa0, pb2, accp[0][2]);
            FFMA2(accp[0][3], pa0, pb3, accp[0][3]);
            FFMA2(accp[1][0], pa1, pb0, accp[1][0]);
            FFMA2(accp[1][1], pa1, pb1, accp[1][1]);
            FFMA2(accp[1][2], pa1, pb2, accp[1][2]);
            FFMA2(accp[1][3], pa1, pb3, accp[1][3]);
            FFMA2(accp[2][0], pa2, pb0, accp[2][0]);
            FFMA2(accp[2][1], pa2, pb1, accp[2][1]);
            FFMA2(accp[2][2], pa2, pb2, accp[2][2]);
            FFMA2(accp[2][3], pa2, pb3, accp[2][3]);
            FFMA2(accp[3][0], pa3, pb0, accp[3][0]);
            FFMA2(accp[3][1], pa3, pb1, accp[3][1]);
            FFMA2(accp[3][2], pa3, pb2, accp[3][2]);
            FFMA2(accp[3][3], pa3, pb3, accp[3][3]);
        }

        // fold this 4x8 tile of distances into per-token best
        if ((m & 3) == 3) {
            float esq[8];
#pragma unroll
            for (int j = 0; j < 8; j++) esq[j] = g_esq[cc + tx * 8 + j];
#pragma unroll
            for (int i = 0; i < 4; i++) {
                float xsq = sxsq[ty * 4 + i];
                float dot[8];
#pragma unroll
                for (int j = 0; j < 4; j++) {
                    unsigned lo, hi;
                    UNPACK2(lo, hi, accp[i][j]);
                    dot[2 * j]     = __uint_as_float(lo);
                    dot[2 * j + 1] = __uint_as_float(hi);
                }
                float bd = __int_as_float(0x7f800000);
                int bi = 0;
#pragma unroll
                for (int j = 0; j < 8; j++) {
                    // (x^2 - 2*dot) + e^2, exactly the reference association
                    float d = __fadd_rn(__fadd_rn(xsq, -__fmul_rn(2.0f, dot[j])), esq[j]);
                    if (d < bd) { bd = d; bi = cc + tx * 8 + j; }   // strict < keeps first min
                }
                unsigned long long key =
                    ((unsigned long long)__float_as_uint(bd) << 32) | (unsigned)bi;
                atomicMin(&best[ty * 4 + i], key);
            }
        }

        // make Bs safe to overwrite, then store the prefetched chunk
        __syncthreads();
        if (m < 31) {
#pragma unroll
            for (int i = 0; i < 8; i++) {
                int t = tid + i * 256;
                int code = t >> 4;
                int k4   = (t & 15) << 2;
                Bs[(k4 + 0) * BS_STRIDE + code] = breg[i].x;
                Bs[(k4 + 1) * BS_STRIDE + code] = breg[i].y;
                Bs[(k4 + 2) * BS_STRIDE + code] = breg[i].z;
                Bs[(k4 + 3) * BS_STRIDE + code] = breg[i].w;
            }
            __syncthreads();
        }
    }
    if (tid < 64)
        g_idx[n0 + tid] = (int)(unsigned)(best[tid] & 0xFFFFFFFFULL);
}

// ---------------------------------------------------------------------------
// Per 32-token tile: write quantized_flat, quantized (transposed), float idx,
// counts, and segment sums of encoded rows.
__global__ __launch_bounds__(256) void scatter_kernel(
    const float* __restrict__ enc, const float* __restrict__ emb,
    float* __restrict__ qf, float* __restrict__ quant, float* __restrict__ idx_out)
{
    __shared__ float rows[32][CD + 1];
    __shared__ int sidx[32];
    int tid = threadIdx.x;
    int n0  = blockIdx.x * 32;

    if (tid < 32) {
        int idx = g_idx[n0 + tid];
        sidx[tid] = idx;
        idx_out[n0 + tid] = (float)idx;
        atomicAdd(&g_counts[idx], 1);
    }
    __syncthreads();

    for (int r = 0; r < 32; r++) {
        int idx = sidx[r];
        float e = emb[(((size_t)idx) << 8) + tid];
        float x = enc[(((size_t)(n0 + r)) << 8) + tid];
        // straight-through: x + (e - x), matching reference rounding
        float qv = __fadd_rn(x, __fadd_rn(e, -x));
        rows[r][tid] = qv;
        qf[(((size_t)(n0 + r)) << 8) + tid] = qv;
        atomicAdd(&g_segsum[(((size_t)idx) << 8) + tid], x);
    }
    __syncthreads();

    int b   = n0 >> 12;
    int hw0 = n0 & 4095;
    int x   = tid & 31;
    for (int c = tid >> 5; c < CD; c += 8)
        quant[(((size_t)b << 8) + c) * HWSZ + hw0 + x] = rows[x][c];
}

// ---------------------------------------------------------------------------
__global__ void usage_kernel(const float* __restrict__ usage_in,
                             float* __restrict__ out_usage)
{
    int k = threadIdx.x;   // 1024 threads
    float u = __fadd_rn(__fmul_rn(usage_in[k], DECAYF),
                        __fmul_rn((float)g_counts[k], OMD));
    __shared__ float red[32];
    __shared__ float n_sh;
    float v = u;
#pragma unroll
    for (int o = 16; o > 0; o >>= 1) v += __shfl_down_sync(0xffffffffu, v, o);
    if ((k & 31) == 0) red[k >> 5] = v;
    __syncthreads();
    if (k < 32) {
        float s = red[k];
#pragma unroll
        for (int o = 16; o > 0; o >>= 1) s += __shfl_down_sync(0xffffffffu, s, o);
        if (k == 0) n_sh = s;
    }
    __syncthreads();
    float n = n_sh;
    float nu = __fmul_rn(__fdiv_rn(__fadd_rn(u, EPSF), __fadd_rn(n, KEPSF)), n);
    out_usage[k] = nu;
    g_usage[k] = nu;
}

__global__ void final_kernel(const float* __restrict__ code_avg,
                             float* __restrict__ new_avg,
                             float* __restrict__ new_emb)
{
    int k = blockIdx.x, c = threadIdx.x;
    size_t i = (((size_t)k) << 8) + c;
    float avg = __fadd_rn(__fmul_rn(code_avg[i], DECAYF),
                          __fmul_rn(OMD, g_segsum[i]));
    new_avg[i] = avg;
    new_emb[i] = __fdiv_rn(avg, g_usage[k]);
}

// ---------------------------------------------------------------------------
extern "C" void kernel_launch(void* const* d_in, const int* in_sizes, int n_in,
                              void* d_out, int out_size)
{
    const float* z        = (const float*)d_in[0];
    const float* emb      = (const float*)d_in[1];
    const float* usage    = (const float*)d_in[2];
    const float* code_avg = (const float*)d_in[3];

    float* out       = (float*)d_out;
    float* enc       = out;                                   // [N, 256]
    float* qf        = enc + (size_t)NTOK * CD;               // [N, 256]
    float* idx_out   = qf + (size_t)NTOK * CD;                // [N]
    float* quant     = idx_out + NTOK;                        // [B, 256, H, W]
    float* new_emb   = quant + (size_t)NTOK * CD;             // [K, 256]
    float* new_usage = new_emb + (size_t)KCODE * CD;          // [K]
    float* new_avg   = new_usage + KCODE;                     // [K, 256]

    cudaFuncSetAttribute(argmin_kernel,
                         cudaFuncAttributeMaxDynamicSharedMemorySize, ARGMIN_SMEM);

    // order chosen so argmin_kernel is launch index 3 (the slot ncu captures)
    esq_kernel<<<KCODE, 64>>>(emb);
    transpose_kernel<<<dim3(HWSZ / 32, CD / 32, NB), dim3(32, 8)>>>(z, enc);
    zero_kernel<<<KCODE, 256>>>();
    argmin_kernel<<<NTOK / 64, 256, ARGMIN_SMEM>>>(enc, emb);
    scatter_kernel<<<NTOK / 32, 256>>>(enc, emb, qf, quant, idx_out);
    usage_kernel<<<1, 1024>>>(usage, new_usage);
    final_kernel<<<KCODE, CD>>>(code_avg, new_avg, new_emb);
}